// round 14
// baseline (speedup 1.0000x reference)
#include <cuda_runtime.h>
#include <math.h>

// DAGMixer R13: 4 rows per CTA with R10's per-thread footprint (R12 + fix:
// each 512-thread half has 16 warps, not 8).
//   logits[row] = dot(orig[row], W[0:H]) + dot(dag[row], W[H:2H]) + b
//   gate = sigmoid(logits); mixed[row] = orig + gate*(dag - orig)
// rows = B*T = 16384 (divisible by 4), H = 2048 (fp32).
//
// Grid = rows/4, 1024 threads, 2 CTAs/SM (full 2048 thr/SM; live set is
// 16 floats/thread, same as R10 -> regs 32). Half of the CTA (tid<512)
// covers rows A,A+1; the other half rows A+2,A+3 — BAR/reduce/sigmoid dead
// window paid once per 64KB of traffic at full occupancy (R11 showed 4
// rows/thread kills occupancy). Four gate chains finalized in parallel by
// warps 0-3.

#define THREADS 1024
#define H_DIM   2048
#define F4_ROW  (H_DIM / 4)     // 512 float4 per row
#define ROWS_PER_CTA 4
#define HWARPS  16              // warps per half (512/32)

__global__ __launch_bounds__(THREADS, 2)
void dagmixer_kernel(const float* __restrict__ orig,
                     const float* __restrict__ dag,
                     const float* __restrict__ w,     // [2H]: W_o then W_d
                     const float* __restrict__ bgate, // [1]
                     float* __restrict__ mixed,       // [rows*H]
                     float* __restrict__ gate_out)    // [rows]
{
    const int rowA = blockIdx.x * ROWS_PER_CTA;
    const int tid  = threadIdx.x;
    const int half = tid >> 9;        // 0: rows A,A+1   1: rows A+2,A+3
    const int t    = tid & 511;       // float4 index within a row

    // This thread's two rows.
    const size_t base = ((size_t)rowA + 2 * half) * H_DIM;
    const float4* __restrict__ oA = (const float4*)(orig + base);
    const float4* __restrict__ dA = (const float4*)(dag  + base);

    const float4 ovA = oA[t];
    const float4 dvA = dA[t];
    const float4 ovB = oA[F4_ROW + t];
    const float4 dvB = dA[F4_ROW + t];

    // W loaded at index t by both halves (second half hits L1).
    const float4 a = ((const float4*)w)[t];
    const float4 c = ((const float4*)(w + H_DIM))[t];

    float pA = ovA.x * a.x + ovA.y * a.y + ovA.z * a.z + ovA.w * a.w
             + dvA.x * c.x + dvA.y * c.y + dvA.z * c.z + dvA.w * c.w;
    float pB = ovB.x * a.x + ovB.y * a.y + ovB.z * a.z + ovB.w * a.w
             + dvB.x * c.x + dvB.y * c.y + dvB.z * c.z + dvB.w * c.w;

    #pragma unroll
    for (int off = 16; off > 0; off >>= 1) {
        pA += __shfl_xor_sync(0xffffffff, pA, off);
        pB += __shfl_xor_sync(0xffffffff, pB, off);
    }

    // ws[row-in-CTA][warp-within-half]
    __shared__ float ws[ROWS_PER_CTA][HWARPS];
    __shared__ float gate_sh[ROWS_PER_CTA];
    const int lane = tid & 31;
    const int hwid = (tid >> 5) & (HWARPS - 1);   // warp index within half
    if (lane == 0) {
        ws[2 * half + 0][hwid] = pA;
        ws[2 * half + 1][hwid] = pB;
    }
    __syncthreads();

    // Row r finalized by lane 0 of warp r (warps 0-3, parallel chains).
    const int wid = tid >> 5;
    if (lane == 0 && wid < ROWS_PER_CTA) {
        float s = bgate[0];
        #pragma unroll
        for (int i = 0; i < HWARPS; i++) s += ws[wid][i];
        const float g = 1.0f / (1.0f + __expf(-s));
        gate_sh[wid] = g;
        gate_out[rowA + wid] = g;
    }
    __syncthreads();

    const float gA = gate_sh[2 * half + 0];
    const float gB = gate_sh[2 * half + 1];

    float4* __restrict__ m = (float4*)(mixed + base);
    float4 r;
    r.x = ovA.x + gA * (dvA.x - ovA.x);
    r.y = ovA.y + gA * (dvA.y - ovA.y);
    r.z = ovA.z + gA * (dvA.z - ovA.z);
    r.w = ovA.w + gA * (dvA.w - ovA.w);
    m[t] = r;

    r.x = ovB.x + gB * (dvB.x - ovB.x);
    r.y = ovB.y + gB * (dvB.y - ovB.y);
    r.z = ovB.z + gB * (dvB.z - ovB.z);
    r.w = ovB.w + gB * (dvB.w - ovB.w);
    m[F4_ROW + t] = r;
}

extern "C" void kernel_launch(void* const* d_in, const int* in_sizes, int n_in,
                              void* d_out, int out_size)
{
    const float* orig  = (const float*)d_in[0];  // original_hidden [B,T,H]
    const float* dag   = (const float*)d_in[1];  // dag_hidden      [B,T,H]
    const float* wgate = (const float*)d_in[2];  // W_gate          [2H,1]
    const float* bgate = (const float*)d_in[3];  // b_gate          [1]

    const int total = in_sizes[0];               // B*T*H
    const int rows  = total / H_DIM;             // B*T (divisible by 4)

    float* mixed    = (float*)d_out;             // first B*T*H floats
    float* gate_out = (float*)d_out + total;     // then B*T gate values

    dagmixer_kernel<<<rows / ROWS_PER_CTA, THREADS>>>(orig, dag, wgate, bgate,
                                                      mixed, gate_out);
}

// round 16
// speedup vs baseline: 1.0925x; 1.0925x over previous
#include <cuda_runtime.h>
#include <math.h>

// DAGMixer R15: R10 (best: ncu 54.3us, DRAM 82.0%) + producer/consumer
// named-barrier split so each warp blocks at most once per CTA.
//   logits[row] = dot(orig[row], W[0:H]) + dot(dag[row], W[H:2H]) + b
//   gate = sigmoid(logits); mixed[row] = orig + gate*(dag - orig)
// rows = B*T = 16384 (even), H = 2048 (fp32).
//
// Grid = rows/2, 512 threads, 4 CTAs/SM (full occupancy — R11/R13 showed
// <4 CTAs/SM collapses DRAM% regardless of thread occupancy). Thread t
// covers float4 t of both rows; 16 live data floats/thread (regs 32).
// Barrier protocol:
//   bar 1 (id 1, 512): warps 2-15 ARRIVE (non-blocking), warps 0-1 SYNC.
//   bar 2 (id 2, 512): warps 0-1 ARRIVE after publishing gates (then mix
//   immediately with register gates), warps 2-15 SYNC.

#define THREADS 512
#define H_DIM   2048
#define F4_ROW  (H_DIM / 4)   // 512 float4 per row = 1 per thread
#define NWARP   (THREADS / 32)

#define BAR_ARRIVE(id) asm volatile("bar.arrive %0, %1;" :: "r"(id), "r"(THREADS) : "memory")
#define BAR_SYNC(id)   asm volatile("bar.sync %0, %1;"   :: "r"(id), "r"(THREADS) : "memory")

__global__ __launch_bounds__(THREADS, 4)
void dagmixer_kernel(const float* __restrict__ orig,
                     const float* __restrict__ dag,
                     const float* __restrict__ w,     // [2H]: W_o then W_d
                     const float* __restrict__ bgate, // [1]
                     float* __restrict__ mixed,       // [rows*H]
                     float* __restrict__ gate_out)    // [rows]
{
    const int rowA = blockIdx.x * 2;
    const int tid  = threadIdx.x;

    const float4* __restrict__ oA = (const float4*)(orig + (size_t)rowA * H_DIM);
    const float4* __restrict__ dA = (const float4*)(dag  + (size_t)rowA * H_DIM);
    const float4* __restrict__ oB = oA + F4_ROW;
    const float4* __restrict__ dB = dA + F4_ROW;

    // Row data: 4 float4 live across the barriers (16 floats).
    const float4 ovA = oA[tid];
    const float4 dvA = dA[tid];
    const float4 ovB = oB[tid];
    const float4 dvB = dB[tid];

    // W loaded once per CTA, consumed immediately (temporaries).
    const float4 a = ((const float4*)w)[tid];
    const float4 c = ((const float4*)(w + H_DIM))[tid];

    float pA = ovA.x * a.x + ovA.y * a.y + ovA.z * a.z + ovA.w * a.w
             + dvA.x * c.x + dvA.y * c.y + dvA.z * c.z + dvA.w * c.w;
    float pB = ovB.x * a.x + ovB.y * a.y + ovB.z * a.z + ovB.w * a.w
             + dvB.x * c.x + dvB.y * c.y + dvB.z * c.z + dvB.w * c.w;

    // Warp reduce both partials (interleaved shfl chains).
    #pragma unroll
    for (int off = 16; off > 0; off >>= 1) {
        pA += __shfl_xor_sync(0xffffffff, pA, off);
        pB += __shfl_xor_sync(0xffffffff, pB, off);
    }

    __shared__ float wsA[NWARP];
    __shared__ float wsB[NWARP];
    __shared__ float gate_sh[2];
    const int wid  = tid >> 5;
    const int lane = tid & 31;
    if (lane == 0) { wsA[wid] = pA; wsB[wid] = pB; }

    if (wid < 2) {
        // Finalize warps: wait for all warpsums, compute gate, publish,
        // arrive (non-blocking), then mix with the register-held gate.
        BAR_SYNC(1);

        float gA_r, gB_r;
        if (lane == 0) {
            float s = bgate[0];
            float* ws = (wid == 0) ? wsA : wsB;
            #pragma unroll
            for (int i = 0; i < NWARP; i++) s += ws[i];
            const float g = 1.0f / (1.0f + __expf(-s));
            gate_sh[wid] = g;
        }
        BAR_ARRIVE(2);
        // gate_out store off the release path.
        if (lane == 0) gate_out[rowA + wid] = gate_sh[wid];

        // These warps read gate_sh they just published (their own write for
        // their row; the sibling's via smem — both complete before arrive?
        // The sibling's may not be: so read via smem only AFTER both lane0
        // writes. Use a warp-pair handshake: each finalize warp reads its
        // OWN gate from smem (written by its lane0, visible within warp
        // after __syncwarp) and the sibling's gate is needed too.
        // Simplest safe order: both gates are read after BAR_SYNC by
        // consumer warps; finalize warps use __shfl within warp for own
        // gate and read sibling's after a syncwarp-pair via bar2 ordering
        // does NOT cover them. So: finalize warps also need both gates ->
        // take them from smem after a small spin-free path: warp 0 needs
        // gate_sh[1] (written by warp 1). Order not guaranteed -> use
        // BAR_SYNC(3) between the two finalize warps only (count 64).
        asm volatile("bar.sync 3, 64;" ::: "memory");
        gA_r = gate_sh[0];
        gB_r = gate_sh[1];

        float4* __restrict__ mA = (float4*)(mixed + (size_t)rowA * H_DIM);
        float4* __restrict__ mB = mA + F4_ROW;
        float4 r;
        r.x = ovA.x + gA_r * (dvA.x - ovA.x);
        r.y = ovA.y + gA_r * (dvA.y - ovA.y);
        r.z = ovA.z + gA_r * (dvA.z - ovA.z);
        r.w = ovA.w + gA_r * (dvA.w - ovA.w);
        mA[tid] = r;
        r.x = ovB.x + gB_r * (dvB.x - ovB.x);
        r.y = ovB.y + gB_r * (dvB.y - ovB.y);
        r.z = ovB.z + gB_r * (dvB.z - ovB.z);
        r.w = ovB.w + gB_r * (dvB.w - ovB.w);
        mB[tid] = r;
    } else {
        // Streaming warps: signal warpsum published (non-blocking), block
        // only once waiting for gates.
        BAR_ARRIVE(1);
        BAR_SYNC(2);

        const float gA = gate_sh[0];
        const float gB = gate_sh[1];

        float4* __restrict__ mA = (float4*)(mixed + (size_t)rowA * H_DIM);
        float4* __restrict__ mB = mA + F4_ROW;
        float4 r;
        r.x = ovA.x + gA * (dvA.x - ovA.x);
        r.y = ovA.y + gA * (dvA.y - ovA.y);
        r.z = ovA.z + gA * (dvA.z - ovA.z);
        r.w = ovA.w + gA * (dvA.w - ovA.w);
        mA[tid] = r;
        r.x = ovB.x + gB * (dvB.x - ovB.x);
        r.y = ovB.y + gB * (dvB.y - ovB.y);
        r.z = ovB.z + gB * (dvB.z - ovB.z);
        r.w = ovB.w + gB * (dvB.w - ovB.w);
        mB[tid] = r;
    }
}

extern "C" void kernel_launch(void* const* d_in, const int* in_sizes, int n_in,
                              void* d_out, int out_size)
{
    const float* orig  = (const float*)d_in[0];  // original_hidden [B,T,H]
    const float* dag   = (const float*)d_in[1];  // dag_hidden      [B,T,H]
    const float* wgate = (const float*)d_in[2];  // W_gate          [2H,1]
    const float* bgate = (const float*)d_in[3];  // b_gate          [1]

    const int total = in_sizes[0];               // B*T*H
    const int rows  = total / H_DIM;             // B*T (even)

    float* mixed    = (float*)d_out;             // first B*T*H floats
    float* gate_out = (float*)d_out + total;     // then B*T gate values

    dagmixer_kernel<<<rows / 2, THREADS>>>(orig, dag, wgate, bgate, mixed, gate_out);
}